// round 10
// baseline (speedup 1.0000x reference)
#include <cuda_runtime.h>
#include <stdint.h>

// Problem constants (from reference)
#define MASS_H2O   18.01056f
#define MASS_NH3   17.02655f
#define MAX_MZ     30000
#define WINDOW     10
#define VOCAB      26
#define BATCH      32768
#define IONS       8

#define TOTAL_GROUPS     (BATCH * VOCAB)               // 851,968
#define TILE_GROUPS      1024
#define NUM_TILES        (TOTAL_GROUPS / TILE_GROUPS)  // 832 exactly
#define WINDOWS_PER_TILE (TILE_GROUPS * IONS)          // 8192
#define ELEMS_PER_TILE   (WINDOWS_PER_TILE * WINDOW)   // 81920
#define VEC2_PER_TILE    (ELEMS_PER_TILE / 2)          // 40960
#define THREADS          1024
#define VEC2_PER_THREAD  (VEC2_PER_TILE / THREADS)     // 40

#define SPEC_FLOATS_PAD  30016                  // 30000 + 16 zero pad
#define SPEC_BYTES       (SPEC_FLOATS_PAD * 4)  // 120,064
#define METABUF          (WINDOWS_PER_TILE + 4)
#define META_BYTES       (2 * METABUF * 4)      // double buffer: 65,568
#define SMEM_BYTES       (SPEC_BYTES + META_BYTES)     // 185,632

#define ZERO_IDX    30000                       // points at zero pad
#define GRID_BLOCKS 152

// One ion-variant window base from c (already cb or cy). EXACT reference
// arithmetic: variant first (single rounding), then *10, round-half-even.
__device__ __forceinline__
int one_meta(float c, int jj, bool vok)
{
    float m;
    if      (jj == 1) m = c - MASS_H2O;
    else if (jj == 2) m = c - MASS_NH3;
    else if (jj == 3) m = c * 0.5f;
    else              m = c;
    const int  idx  = __float2int_rn(m * 10.0f) - (WINDOW / 2);
    const bool keep = (idx >= 0) && (idx <= MAX_MZ - WINDOW) && vok;
    return keep ? idx : ZERO_IDX;
}

// Build 4 windows (one group-half) as an int4 for a single STS.128.
__device__ __forceinline__
int4 meta4(float pm, float pf, float ms, int v, int half, int dir)
{
    float cb, cy;
    if (dir == 0) { cb = pf + ms; cy = pm - cb; }
    else          { cy = pf + ms; cb = pm - cy; }
    const float c   = half ? cy : cb;
    const bool  vok = (v >= 3);
    int4 mw;
    mw.x = one_meta(c, 0, vok);
    mw.y = one_meta(c, 1, vok);
    mw.z = one_meta(c, 2, vok);
    mw.w = one_meta(c, 3, vok);
    return mw;
}

__global__ void __launch_bounds__(THREADS, 1)
intensity_kernel(const float* __restrict__ pepmass,
                 const float* __restrict__ prefix_mass,
                 const float* __restrict__ masses,
                 const float* __restrict__ spectrum,
                 const int*   __restrict__ dir_ptr,
                 float* __restrict__ out)
{
    extern __shared__ unsigned char smem_raw[];
    float* spec = reinterpret_cast<float*>(smem_raw);
    int*   meta = reinterpret_cast<int*>(smem_raw + SPEC_BYTES);

    const int tid  = threadIdx.x;
    const int dir  = dir_ptr ? __ldg(dir_ptr) : 0;
    const int half = tid & 1;            // same parity for both owned slots
    const int glA  = tid >> 1;           // slot A: int4 index tid
    const int glB  = 512 + (tid >> 1);   // slot B: int4 index tid+1024

    // ---- stage spectrum into SMEM (zero the 16-float pad) ----
    {
        const float4* s4 = reinterpret_cast<const float4*>(spectrum);
        float4*       d4 = reinterpret_cast<float4*>(spec);
        const float4  z4 = make_float4(0.f, 0.f, 0.f, 0.f);
        #pragma unroll 2
        for (int i = tid; i < SPEC_FLOATS_PAD / 4; i += THREADS)
            d4[i] = (i < MAX_MZ / 4) ? s4[i] : z4;
    }

    // ---- prologue: prefetch tile-0 inputs (6 LDGs per thread) ----
    float pmA, pfA, msA, pmB, pfB, msB;
    int   vA, vB;
    {
        const int gA = blockIdx.x * TILE_GROUPS + glA;
        const int bA = gA / VOCAB;  vA = gA - bA * VOCAB;
        pmA = __ldg(pepmass + bA); pfA = __ldg(prefix_mass + bA); msA = __ldg(masses + vA);
        const int gB = blockIdx.x * TILE_GROUPS + glB;
        const int bB = gB / VOCAB;  vB = gB - bB * VOCAB;
        pmB = __ldg(pepmass + bB); pfB = __ldg(prefix_mass + bB); msB = __ldg(masses + vB);
    }

    int parity = 0;
    for (int tile = blockIdx.x; tile < NUM_TILES; tile += GRID_BLOCKS) {
        int* mb = meta + parity * METABUF;
        parity ^= 1;

        // ---- publish this tile's metadata: 8 windows, two STS.128 ----
        reinterpret_cast<int4*>(mb)[tid]           = meta4(pmA, pfA, msA, vA, half, dir);
        reinterpret_cast<int4*>(mb)[tid + THREADS] = meta4(pmB, pfB, msB, vB, half, dir);
        __syncthreads();   // (first iteration: also covers spectrum staging)

        // ---- issue NEXT tile's 6 loads; consumers only at next loop top ----
        {
            int nt = tile + GRID_BLOCKS;
            if (nt >= NUM_TILES) nt = tile;          // clamp: harmless reload
            const int gA = nt * TILE_GROUPS + glA;
            const int bA = gA / VOCAB;  vA = gA - bA * VOCAB;
            pmA = __ldg(pepmass + bA); pfA = __ldg(prefix_mass + bA); msA = __ldg(masses + vA);
            const int gB = nt * TILE_GROUPS + glB;
            const int bB = gB / VOCAB;  vB = gB - bB * VOCAB;
            pmB = __ldg(pepmass + bB); pfB = __ldg(prefix_mass + bB); msB = __ldg(masses + vB);
        }

        // ---------- Phase 2: 40 float2 per thread, SMEM gather ----------
        // A float2 at even element offset NEVER straddles a window
        // (w0 in {0,2,4,6,8}; w0+1 <= 9) -> zero crossing logic.
        float2* out2 = reinterpret_cast<float2*>(out) + tile * VEC2_PER_TILE;

        #pragma unroll 10
        for (int k = 0; k < VEC2_PER_THREAD; ++k) {
            const int q   = tid + k * THREADS;       // float2 index, 0..40959
            const unsigned win = (unsigned)q / 5u;   // window = (2q)/10
            const int w0  = (q - (int)win * 5) * 2;  // in {0,2,4,6,8}

            const int a = mb[win] + w0;              // LDS.32 meta (broadcast)
            float2 o;
            o.x = spec[a];
            o.y = spec[a + 1];
            __stcs(out2 + q, o);                     // streaming STG.64
        }
        // no trailing sync: double-buffered metadata (the barrier above
        // proves all readers of the other buffer finished before rewrite)
    }
}

extern "C" void kernel_launch(void* const* d_in, const int* in_sizes, int n_in,
                              void* d_out, int out_size)
{
    const float* spectrum    = (const float*)d_in[0];
    const float* pepmass     = (const float*)d_in[1];
    const float* prefix_mass = (const float*)d_in[2];
    const float* masses      = (const float*)d_in[3];
    const int*   dir_ptr     = (n_in >= 5) ? (const int*)d_in[4] : nullptr;
    float*       out         = (float*)d_out;

    cudaFuncSetAttribute(intensity_kernel,
                         cudaFuncAttributeMaxDynamicSharedMemorySize, SMEM_BYTES);

    intensity_kernel<<<GRID_BLOCKS, THREADS, SMEM_BYTES>>>(
        pepmass, prefix_mass, masses, spectrum, dir_ptr, out);
}

// round 11
// speedup vs baseline: 1.0885x; 1.0885x over previous
#include <cuda_runtime.h>
#include <stdint.h>

// Problem constants (from reference)
#define MASS_H2O   18.01056f
#define MASS_NH3   17.02655f
#define MAX_MZ     30000
#define WINDOW     10
#define VOCAB      26
#define BATCH      32768
#define IONS       8

#define TOTAL_GROUPS     (BATCH * VOCAB)               // 851,968
#define TILE_GROUPS      512
#define NUM_TILES        (TOTAL_GROUPS / TILE_GROUPS)  // 1664 exactly
#define WINDOWS_PER_TILE (TILE_GROUPS * IONS)          // 4096
#define ELEMS_PER_TILE   (WINDOWS_PER_TILE * WINDOW)   // 40960
#define VEC2_PER_TILE    (ELEMS_PER_TILE / 2)          // 20480
#define THREADS          1024
#define VEC2_PER_THREAD  (VEC2_PER_TILE / THREADS)     // 20
#define BATCH_N          10                            // metas prefetched per batch

#define SPEC_FLOATS_PAD  30016                  // 30000 + 16 zero pad
#define SPEC_BYTES       (SPEC_FLOATS_PAD * 4)  // 120,064
#define METABUF          (WINDOWS_PER_TILE + 4)
#define META_BYTES       (2 * METABUF * 4)      // double buffer: 32,800
#define SMEM_BYTES       (SPEC_BYTES + META_BYTES)     // 152,864

#define ZERO_IDX    30000                       // points at zero pad
#define GRID_BLOCKS 152

// One ion-variant window base from c (already cb or cy). EXACT reference
// arithmetic: variant first (single rounding), then *10, round-half-even.
__device__ __forceinline__
int one_meta(float c, int jj, bool vok)
{
    float m;
    if      (jj == 1) m = c - MASS_H2O;
    else if (jj == 2) m = c - MASS_NH3;
    else if (jj == 3) m = c * 0.5f;
    else              m = c;
    const int  idx  = __float2int_rn(m * 10.0f) - (WINDOW / 2);
    const bool keep = (idx >= 0) && (idx <= MAX_MZ - WINDOW) && vok;
    return keep ? idx : ZERO_IDX;
}

__global__ void __launch_bounds__(THREADS, 1)
intensity_kernel(const float* __restrict__ pepmass,
                 const float* __restrict__ prefix_mass,
                 const float* __restrict__ masses,
                 const float* __restrict__ spectrum,
                 const int*   __restrict__ dir_ptr,
                 float* __restrict__ out)
{
    extern __shared__ unsigned char smem_raw[];
    float* spec = reinterpret_cast<float*>(smem_raw);
    int*   meta = reinterpret_cast<int*>(smem_raw + SPEC_BYTES);

    const int tid  = threadIdx.x;
    const int dir  = dir_ptr ? __ldg(dir_ptr) : 0;
    const int gl   = tid >> 1;          // group within tile owned by thread
    const int half = tid & 1;           // 0 -> ions 0..3 (cb), 1 -> ions 4..7 (cy)

    // ---- stage spectrum into SMEM (zero the 16-float pad) ----
    {
        const float4* s4 = reinterpret_cast<const float4*>(spectrum);
        float4*       d4 = reinterpret_cast<float4*>(spec);
        const float4  z4 = make_float4(0.f, 0.f, 0.f, 0.f);
        #pragma unroll 2
        for (int i = tid; i < SPEC_FLOATS_PAD / 4; i += THREADS)
            d4[i] = (i < MAX_MZ / 4) ? s4[i] : z4;
    }

    // ---- prologue: prefetch tile-0 inputs (3 LDGs per thread) ----
    float pm, pf, ms;
    int   v;
    {
        const int g = blockIdx.x * TILE_GROUPS + gl;
        const int b = g / VOCAB;  v = g - b * VOCAB;
        pm = __ldg(pepmass + b); pf = __ldg(prefix_mass + b); ms = __ldg(masses + v);
    }

    int parity = 0;
    for (int tile = blockIdx.x; tile < NUM_TILES; tile += GRID_BLOCKS) {
        int* mb = meta + parity * METABUF;
        parity ^= 1;

        // ---- publish this tile's metadata: 4 windows, one STS.128 ----
        {
            float cb, cy;
            if (dir == 0) { cb = pf + ms; cy = pm - cb; }
            else          { cy = pf + ms; cb = pm - cy; }
            const float c   = half ? cy : cb;
            const bool  vok = (v >= 3);
            int4 mw;
            mw.x = one_meta(c, 0, vok);
            mw.y = one_meta(c, 1, vok);
            mw.z = one_meta(c, 2, vok);
            mw.w = one_meta(c, 3, vok);
            reinterpret_cast<int4*>(mb)[tid] = mw;   // windows 4*tid..4*tid+3
        }
        __syncthreads();   // (first iteration: also covers spectrum staging)

        // ---- issue NEXT tile's 3 loads; consumers only at next loop top ----
        {
            int nt = tile + GRID_BLOCKS;
            if (nt >= NUM_TILES) nt = tile;          // clamp: harmless reload
            const int g = nt * TILE_GROUPS + gl;
            const int b = g / VOCAB;  v = g - b * VOCAB;
            pm = __ldg(pepmass + b); pf = __ldg(prefix_mass + b); ms = __ldg(masses + v);
        }

        // ---------- Phase 2: 20 float2 per thread, batched meta prefetch ----
        // A float2 at even element offset NEVER straddles a window.
        // Batch structure: 10 independent meta LDS first (one latency,
        // 10-deep MLP), then 10 independent gather+store chains.
        float2* out2 = reinterpret_cast<float2*>(out) + tile * VEC2_PER_TILE;

        #pragma unroll
        for (int kk = 0; kk < VEC2_PER_THREAD / BATCH_N; ++kk) {
            int addr[BATCH_N];

            #pragma unroll
            for (int j = 0; j < BATCH_N; ++j) {
                const int q = tid + (kk * BATCH_N + j) * THREADS;
                const unsigned win = (unsigned)q / 5u;   // window = (2q)/10
                const int w0 = (q - (int)win * 5) * 2;   // in {0,2,4,6,8}
                addr[j] = mb[win] + w0;                  // LDS.32 meta burst
            }

            #pragma unroll
            for (int j = 0; j < BATCH_N; ++j) {
                const int q = tid + (kk * BATCH_N + j) * THREADS;
                float2 o;
                o.x = spec[addr[j]];
                o.y = spec[addr[j] + 1];
                __stcs(out2 + q, o);                     // streaming STG.64
            }
        }
        // no trailing sync: double-buffered metadata (the barrier above
        // proves all readers of the other buffer finished before rewrite)
    }
}

extern "C" void kernel_launch(void* const* d_in, const int* in_sizes, int n_in,
                              void* d_out, int out_size)
{
    const float* spectrum    = (const float*)d_in[0];
    const float* pepmass     = (const float*)d_in[1];
    const float* prefix_mass = (const float*)d_in[2];
    const float* masses     = (const float*)d_in[3];
    const int*   dir_ptr     = (n_in >= 5) ? (const int*)d_in[4] : nullptr;
    float*       out         = (float*)d_out;

    cudaFuncSetAttribute(intensity_kernel,
                         cudaFuncAttributeMaxDynamicSharedMemorySize, SMEM_BYTES);

    intensity_kernel<<<GRID_BLOCKS, THREADS, SMEM_BYTES>>>(
        pepmass, prefix_mass, masses, spectrum, dir_ptr, out);
}